// round 9
// baseline (speedup 1.0000x reference)
#include <cuda_runtime.h>
#include <math.h>

#define VOCAB   50257
#define EMBED   128
#define HIDDEN  128
#define NCLASS  4
#define BB      256
#define TT      512
#define NTOK    (BB * TT)

// ---------------------------------------------------------------- helpers
__device__ __forceinline__ unsigned smem_u32(const void* p) {
    return (unsigned)__cvta_generic_to_shared(p);
}
__device__ __forceinline__ void cp_async16(void* dst, const void* src) {
    asm volatile("cp.async.cg.shared.global [%0], [%1], 16;"
                 :: "r"(smem_u32(dst)), "l"(src));
}
__device__ __forceinline__ void cp_commit() {
    asm volatile("cp.async.commit_group;");
}
__device__ __forceinline__ void cp_wait1() {
    asm volatile("cp.async.wait_group 1;");
}
// packed dual fp32 FMA (sm_103a f32x2 pipe)
__device__ __forceinline__ unsigned long long
fma2(unsigned long long a, unsigned long long b, unsigned long long c) {
    unsigned long long d;
    asm("fma.rn.f32x2 %0, %1, %2, %3;" : "=l"(d) : "l"(a), "l"(b), "l"(c));
    return d;
}
__device__ __forceinline__ float2 unpack2(unsigned long long v) {
    float2 r;
    asm("mov.b64 {%0, %1}, %2;" : "=f"(r.x), "=f"(r.y) : "l"(v));
    return r;
}
__device__ __forceinline__ float fast_tanh(float x) {
    x = fminf(fmaxf(x, -15.0f), 15.0f);
    float e = __expf(2.0f * x);
    return 1.0f - __fdividef(2.0f, e + 1.0f);
}

// interleaved float offset for scalar k within a 128-float row:
// k -> ((k&31)>>2)*16 + (k>>5)*4 + (k&3)
// Property: at dot-step j, the 4 K-quarters' 16B chunks form one 64B span
// (1 LDS wavefront), and 16B cp.async chunks land contiguously.
__device__ __forceinline__ int ilv_off(int k) {
    return ((k & 31) >> 2) * 16 + (k >> 5) * 4 + (k & 3);
}

// 32-float dot for this thread's K-quarter. srcq = (ulonglong2*)row_base + q.
__device__ __forceinline__ float dot32q(
    const ulonglong2* __restrict__ srcq,
    const unsigned long long* __restrict__ w)
{
    unsigned long long a0 = 0, a1 = 0;
    #pragma unroll
    for (int j = 0; j < 8; ++j) {
        ulonglong2 v = srcq[j * 4];
        a0 = fma2(w[2 * j],     v.x, a0);
        a1 = fma2(w[2 * j + 1], v.y, a1);
    }
    float2 u0 = unpack2(a0), u1 = unpack2(a1);
    return (u0.x + u0.y) + (u1.x + u1.y);
}

__device__ __forceinline__ float qreduce(float v) {
    v += __shfl_xor_sync(0xffffffffu, v, 8);
    v += __shfl_xor_sync(0xffffffffu, v, 16);
    return v;
}

// ---------------------------------------------------------------------------
// Fused kernel: embedding gather + x-projection + recurrence, all in one.
// 128 CTAs x 512 threads, 1 CTA/SM, CTA owns batch rows (2*bid, 2*bid+1).
// Thread: warp w (0..15), lane; oid = lane&7, q = lane>>3, out = w*8+oid.
// Holds W_hh[out][q*32..+32) and W_ih[out][q*32..+32) in regs (32 u64).
// Per step t: stage emb token t+2 (cp.async, 3-slot ring, interleaved),
// compute xp[t+1] (kept in regs) + rnn step t for both rows,
// reduce K-quarters via shfl_xor(8)+(16); lanes q==0 do tanh + publish h.
// ---------------------------------------------------------------------------
// shared floats: ids[2*512 ints] | emb[2 rows][3 slots][128] | h[2][2][128] | stg[4096]
#define FS_IDS  0
#define FS_EMB  1024
#define FS_H    (1024 + 768)
#define FS_STG  (1024 + 768 + 512)
#define FS_TOT  (1024 + 768 + 512 + 4096)

__global__ void __launch_bounds__(512, 1) fused_rnn_kernel(
    const int* __restrict__ x, const float* __restrict__ emb,
    const float* __restrict__ W_ih, const float* __restrict__ W_hh,
    const float* __restrict__ b_ih, const float* __restrict__ b_hh,
    const float* __restrict__ h0, float* __restrict__ out_hidden)
{
    extern __shared__ float sh[];
    int*   s_ids = (int*)(sh + FS_IDS);     // [2][512]
    float* s_emb = sh + FS_EMB;             // [2][3][128] interleaved
    float* s_h   = sh + FS_H;               // [2 bufs][2 rows][128] interleaved
    float* s_stg = sh + FS_STG;             // 4096 staging

    const int tid  = threadIdx.x;
    const int lane = tid & 31;
    const int w    = tid >> 5;              // 0..15
    const int oid  = lane & 7;
    const int q    = lane >> 3;
    const int out  = w * 8 + oid;
    const int b0   = blockIdx.x * 2;
    const int ilv  = ilv_off(out);

    // ---- stage token ids for both rows
    for (int i = tid; i < 2 * TT; i += 512) {
        int row = i >> 9, tt = i & 511;
        s_ids[i] = x[(size_t)(b0 + row) * TT + tt];
    }

    // ---- load weight slices into registers (8 coalesced passes)
    unsigned long long wh[16], wi[16];
    for (int p = 0; p < 4; ++p) {
        for (int i = tid; i < 4096; i += 512)
            s_stg[i] = W_hh[p * 4096 + i];
        __syncthreads();
        if ((out >> 5) == p) {
            const unsigned long long* r =
                (const unsigned long long*)(s_stg + (out & 31) * 128 + q * 32);
            #pragma unroll
            for (int k = 0; k < 16; ++k) wh[k] = r[k];
        }
        __syncthreads();
    }
    for (int p = 0; p < 4; ++p) {
        for (int i = tid; i < 4096; i += 512)
            s_stg[i] = W_ih[p * 4096 + i];
        __syncthreads();
        if ((out >> 5) == p) {
            const unsigned long long* r =
                (const unsigned long long*)(s_stg + (out & 31) * 128 + q * 32);
            #pragma unroll
            for (int k = 0; k < 16; ++k) wi[k] = r[k];
        }
        __syncthreads();
    }
    const float bias = b_ih[out] + b_hh[out];

    // ---- init h buffer 0 (interleaved layout) by q==0 lanes
    if (q == 0) {
        s_h[ilv]       = h0[(size_t)b0 * HIDDEN + out];
        s_h[128 + ilv] = h0[(size_t)(b0 + 1) * HIDDEN + out];
    }

    // ---- prologue: stage emb tokens 0 and 1
    const int pr_row = tid >> 5 >= 8 ? 0 : 0;  // (unused marker)
    if (tid < 64) {
        int row = tid >> 5, l = tid & 31;
        int id = s_ids[row * TT + 0];
        cp_async16(s_emb + (row * 3 + 0) * 128 + (l & 7) * 16 + (l >> 3) * 4,
                   emb + (size_t)id * EMBED + l * 4);
    }
    cp_commit();
    if (tid < 64) {
        int row = tid >> 5, l = tid & 31;
        int id = s_ids[row * TT + 1];
        cp_async16(s_emb + (row * 3 + 1) * 128 + (l & 7) * 16 + (l >> 3) * 4,
                   emb + (size_t)id * EMBED + l * 4);
    }
    cp_commit();
    cp_wait1();          // slot 0 complete (per-thread; others trivially pass)
    __syncthreads();     // h0, ids, emb slot 0 visible

    // xp[0] for both rows -> registers
    float xv0, xv1;
    {
        float a = dot32q((const ulonglong2*)(s_emb + 0 * 128) + q, wi);
        float b = dot32q((const ulonglong2*)(s_emb + 3 * 128) + q, wi);
        xv0 = qreduce(a) + bias;
        xv1 = qreduce(b) + bias;
    }

    float hc0 = 0.f, hc1 = 0.f;

    for (int t = 0; t < TT; ++t) {
        // 1. stage emb token t+2 into slot (t+2)%3 (clamped at the tail)
        if (tid < 64) {
            int row = tid >> 5, l = tid & 31;
            int tk = (t + 2 < TT) ? t + 2 : TT - 1;
            int id = s_ids[row * TT + tk];
            cp_async16(s_emb + (row * 3 + (t + 2) % 3) * 128
                           + (l & 7) * 16 + (l >> 3) * 4,
                       emb + (size_t)id * EMBED + l * 4);
        }
        cp_commit();
        cp_wait1();          // slot (t+1)%3 complete
        __syncthreads();     // emb t+1 + h[t] (+ xp regs) coherent CTA-wide

        // 2. compute: xproj token t+1 (both rows) + rnn step t (both rows)
        const int es = (t + 1) % 3;
        const float* hb = s_h + (t & 1) * 256;
        float x0 = dot32q((const ulonglong2*)(s_emb + (0 * 3 + es) * 128) + q, wi);
        float x1 = dot32q((const ulonglong2*)(s_emb + (1 * 3 + es) * 128) + q, wi);
        float r0 = dot32q((const ulonglong2*)(hb) + q, wh);
        float r1 = dot32q((const ulonglong2*)(hb + 128) + q, wh);
        r0 = qreduce(r0);
        r1 = qreduce(r1);
        x0 = qreduce(x0);
        x1 = qreduce(x1);

        if (q == 0) {
            hc0 = fast_tanh(r0 + xv0);
            hc1 = fast_tanh(r1 + xv1);
            float* hn = s_h + ((t + 1) & 1) * 256;
            hn[ilv]       = hc0;
            hn[128 + ilv] = hc1;
        }
        xv0 = x0 + bias;     // becomes xp[t+1] consumed next step
        xv1 = x1 + bias;
        __syncthreads();     // publish h[t+1]
    }

    if (q == 0) {
        out_hidden[(size_t)b0 * HIDDEN + out]       = hc0;
        out_hidden[(size_t)(b0 + 1) * HIDDEN + out] = hc1;
    }
}

// ---------------------------------------------------------------------------
// MLP head. One CTA per batch row.
// ---------------------------------------------------------------------------
__global__ void __launch_bounds__(256) head_kernel(
    const float* __restrict__ hidden, const float* __restrict__ W1,
    const float* __restrict__ b1, const float* __restrict__ W2,
    const float* __restrict__ b2, float* __restrict__ logits)
{
    __shared__ float shH[HIDDEN];
    __shared__ float shM[2 * HIDDEN];
    const int b = blockIdx.x, tid = threadIdx.x;
    if (tid < HIDDEN) shH[tid] = hidden[(size_t)b * HIDDEN + tid];
    __syncthreads();

    float acc = b1[tid];
    const float4* w4 = (const float4*)(W1 + (size_t)tid * HIDDEN);
    const float4* h4 = (const float4*)shH;
    #pragma unroll 8
    for (int k4 = 0; k4 < 32; ++k4) {
        float4 w = w4[k4];
        float4 h = h4[k4];
        acc = fmaf(w.x, h.x, acc);
        acc = fmaf(w.y, h.y, acc);
        acc = fmaf(w.z, h.z, acc);
        acc = fmaf(w.w, h.w, acc);
    }
    shM[tid] = fmaxf(acc, 0.0f);
    __syncthreads();

    if (tid < NCLASS) {
        float a = b2[tid];
        const float* w2 = W2 + (size_t)tid * (2 * HIDDEN);
        #pragma unroll 8
        for (int k = 0; k < 2 * HIDDEN; ++k)
            a = fmaf(shM[k], w2[k], a);
        logits[(size_t)b * NCLASS + tid] = a;
    }
}

// ---------------------------------------------------------------------------
extern "C" void kernel_launch(void* const* d_in, const int* in_sizes, int n_in,
                              void* d_out, int out_size)
{
    const int*   x    = (const int*)  d_in[0];
    const float* h0   = (const float*)d_in[1];
    const float* emb  = (const float*)d_in[2];
    const float* W_ih = (const float*)d_in[3];
    const float* W_hh = (const float*)d_in[4];
    const float* b_ih = (const float*)d_in[5];
    const float* b_hh = (const float*)d_in[6];
    const float* W1   = (const float*)d_in[7];
    const float* b1   = (const float*)d_in[8];
    const float* W2   = (const float*)d_in[9];
    const float* b2   = (const float*)d_in[10];

    float* out    = (float*)d_out;
    float* logits = out;                 // [256*4]
    float* hidden = out + BB * NCLASS;   // [256*128]

    const int smemf = FS_TOT * sizeof(float);   // ~25.6KB

    fused_rnn_kernel<<<BB / 2, 512, smemf>>>(x, emb, W_ih, W_hh,
                                             b_ih, b_hh, h0, hidden);
    head_kernel<<<BB, 256>>>(hidden, W1, b1, W2, b2, logits);
}

// round 10
// speedup vs baseline: 1.1928x; 1.1928x over previous
#include <cuda_runtime.h>
#include <math.h>

#define VOCAB   50257
#define EMBED   128
#define HIDDEN  128
#define NCLASS  4
#define BB      256
#define TT      512
#define NTOK    (BB * TT)

// x_proj scratch [t][b][h] : 64MB device global (no runtime alloc)
__device__ float g_xp[TT * BB * HIDDEN];

// ---------------------------------------------------------------- helpers
__device__ __forceinline__ unsigned smem_u32(const void* p) {
    return (unsigned)__cvta_generic_to_shared(p);
}
__device__ __forceinline__ void cp_async16(void* dst, const void* src) {
    asm volatile("cp.async.cg.shared.global [%0], [%1], 16;"
                 :: "r"(smem_u32(dst)), "l"(src));
}
__device__ __forceinline__ void cp_commit() {
    asm volatile("cp.async.commit_group;");
}
__device__ __forceinline__ void cp_wait1() {
    asm volatile("cp.async.wait_group 1;");
}
__device__ __forceinline__ void cp_wait0() {
    asm volatile("cp.async.wait_group 0;");
}
// packed dual fp32 ops (sm_103a f32x2 pipe)
__device__ __forceinline__ unsigned long long
fma2(unsigned long long a, unsigned long long b, unsigned long long c) {
    unsigned long long d;
    asm("fma.rn.f32x2 %0, %1, %2, %3;" : "=l"(d) : "l"(a), "l"(b), "l"(c));
    return d;
}
__device__ __forceinline__ unsigned long long
add2(unsigned long long a, unsigned long long b) {
    unsigned long long d;
    asm("add.rn.f32x2 %0, %1, %2;" : "=l"(d) : "l"(a), "l"(b));
    return d;
}
__device__ __forceinline__ float2 unpack2(unsigned long long v) {
    float2 r;
    asm("mov.b64 {%0, %1}, %2;" : "=f"(r.x), "=f"(r.y) : "l"(v));
    return r;
}
__device__ __forceinline__ float fast_tanh(float x) {
    x = fminf(fmaxf(x, -15.0f), 15.0f);
    float e = __expf(2.0f * x);
    return 1.0f - __fdividef(2.0f, e + 1.0f);
}

// ---------------------------------------------------------------------------
// Kernel 1 (proven round-6 version, 152us): x_proj = emb[x] @ W_ih^T + bias
// ---------------------------------------------------------------------------
#define XP_GRID  148
#define XP_TPC   886
#define XP_CH    16
#define XP_NC    ((XP_TPC + XP_CH - 1) / XP_CH)   // 56

#define XPS_IDS   0
#define XPS_ACT   896
#define XPS_TOT   (896 + 4096)

__device__ __forceinline__ float2 dot32x2(
    const ulonglong2* __restrict__ srcq,
    const unsigned long long* __restrict__ wA,
    const unsigned long long* __restrict__ wB)
{
    unsigned long long a0 = 0, a1 = 0, b0 = 0, b1 = 0;
    #pragma unroll
    for (int j = 0; j < 8; ++j) {
        ulonglong2 v = srcq[j * 4];
        a0 = fma2(wA[2 * j],     v.x, a0);
        a1 = fma2(wA[2 * j + 1], v.y, a1);
        b0 = fma2(wB[2 * j],     v.x, b0);
        b1 = fma2(wB[2 * j + 1], v.y, b1);
    }
    float2 ua0 = unpack2(a0), ua1 = unpack2(a1);
    float2 ub0 = unpack2(b0), ub1 = unpack2(b1);
    float d0 = (ua0.x + ua0.y) + (ua1.x + ua1.y);
    float d1 = (ub0.x + ub0.y) + (ub1.x + ub1.y);
    d0 += __shfl_xor_sync(0xffffffffu, d0, 8);
    d0 += __shfl_xor_sync(0xffffffffu, d0, 16);
    d1 += __shfl_xor_sync(0xffffffffu, d1, 8);
    d1 += __shfl_xor_sync(0xffffffffu, d1, 16);
    return make_float2(d0, d1);
}

__device__ __forceinline__ void load_wslice(
    const float* __restrict__ s_stg, int o0, int q,
    unsigned long long* __restrict__ wA, unsigned long long* __restrict__ wB)
{
    const unsigned long long* rA =
        (const unsigned long long*)(s_stg + (o0 & 31) * 128 + q * 32);
    const unsigned long long* rB =
        (const unsigned long long*)(s_stg + ((o0 & 31) + 1) * 128 + q * 32);
    #pragma unroll
    for (int k = 0; k < 16; ++k) { wA[k] = rA[k]; wB[k] = rB[k]; }
}

__global__ void __launch_bounds__(512, 1) xproj_kernel(
    const int* __restrict__ x, const float* __restrict__ emb,
    const float* __restrict__ W_ih, const float* __restrict__ b_ih,
    const float* __restrict__ b_hh)
{
    extern __shared__ float sh[];
    int*   s_ids = (int*)(sh + XPS_IDS);
    float* s_act = sh + XPS_ACT;

    const int tid  = threadIdx.x;
    const int lane = tid & 31;
    const int wid  = tid >> 5;
    const int oid  = lane & 7;
    const int q    = lane >> 3;
    const int o0   = ((wid & 7) << 4) + oid * 2;
    const int sub  = wid >> 3;
    const int r0   = blockIdx.x * XP_TPC;

    for (int i = tid; i < 896; i += 512) {
        int r = r0 + i;
        s_ids[i] = (i < XP_TPC && r < NTOK) ? x[r] : 0;
    }

    unsigned long long wA[16], wB[16];
    for (int p = 0; p < 4; ++p) {
        for (int i = tid; i < 4096; i += 512)
            s_act[i] = W_ih[p * 4096 + i];
        __syncthreads();
        if ((o0 >> 5) == p) load_wslice(s_act, o0, q, wA, wB);
        __syncthreads();
    }
    const float bias0 = b_ih[o0] + b_hh[o0];
    const float bias1 = b_ih[o0 + 1] + b_hh[o0 + 1];

    const int st_slot = tid >> 5;
    const int st_k4   = tid & 31;
    const int st_dst  = st_slot * 128 + (st_k4 & 7) * 16 + (st_k4 >> 3) * 4;
    const int st_src  = st_k4 * 4;

    {
        int id = s_ids[st_slot];
        cp_async16(s_act + st_dst, emb + (size_t)id * EMBED + st_src);
        cp_commit();
    }

    for (int c = 0; c < XP_NC; ++c) {
        if (c + 1 < XP_NC) {
            float* dst = s_act + ((c + 1) & 1) * 2048;
            int id = s_ids[(c + 1) * XP_CH + st_slot];
            cp_async16(dst + st_dst, emb + (size_t)id * EMBED + st_src);
            cp_commit();
            cp_wait1();
        } else {
            cp_wait0();
        }
        __syncthreads();

        const float* buf = s_act + (c & 1) * 2048;
        #pragma unroll 2
        for (int j = 0; j < 8; ++j) {
            int slot = sub * 8 + j;
            const ulonglong2* srcq =
                (const ulonglong2*)(buf + slot * 128) + q;
            float2 d = dot32x2(srcq, wA, wB);
            int i_tok = c * XP_CH + slot;
            int r = r0 + i_tok;
            if (q == 0 && i_tok < XP_TPC && r < NTOK) {
                int b = r >> 9, t = r & (TT - 1);
                float2 v = make_float2(d.x + bias0, d.y + bias1);
                *(float2*)(g_xp + ((size_t)t * BB + b) * HIDDEN + o0) = v;
            }
        }
        __syncthreads();
    }
}

// ---------------------------------------------------------------------------
// Kernel 2: recurrence + fused MLP head. 128 CTAs x 128 threads (1 CTA/SM).
// CTA owns 2 batch rows; thread owns output `out` for BOTH rows (weights
// shared). 8 accumulators per row (chain depth 8), packed-add reduce tree,
// 4-deep xp prefetch queue, one __syncthreads per step. Epilogue computes
// the 2 rows' MLP head in-CTA (no separate head kernel).
// ---------------------------------------------------------------------------
// shared floats: h[2 bufs][2 rows][128] | mlp[2][256] | stage[4096]
#define RH_H    0
#define RH_MLP  512
#define RH_STG  1024
#define RH_TOT  (1024 + 4096)

__global__ void __launch_bounds__(128, 1) rnn_head_kernel(
    const float* __restrict__ h0, const float* __restrict__ W_hh,
    const float* __restrict__ W1, const float* __restrict__ b1,
    const float* __restrict__ W2, const float* __restrict__ b2,
    float* __restrict__ logits, float* __restrict__ out_hidden)
{
    extern __shared__ float sh[];
    float* s_h   = sh + RH_H;
    float* s_mlp = sh + RH_MLP;
    float* s_stg = sh + RH_STG;

    const int out = threadIdx.x;         // 0..127
    const int b0  = blockIdx.x * 2;

    // stage W_hh rows -> registers (4 coalesced passes)
    unsigned long long wh[64];
    for (int p = 0; p < 4; ++p) {
        for (int i = out; i < 4096; i += 128)
            s_stg[i] = W_hh[p * 4096 + i];
        __syncthreads();
        if ((out >> 5) == p) {
            const unsigned long long* row =
                (const unsigned long long*)(s_stg + (out & 31) * 128);
            #pragma unroll
            for (int k = 0; k < 64; ++k) wh[k] = row[k];
        }
        __syncthreads();
    }

    s_h[out]       = h0[(size_t)b0 * HIDDEN + out];
    s_h[128 + out] = h0[(size_t)(b0 + 1) * HIDDEN + out];
    __syncthreads();

    const float* xpA = g_xp + (size_t)b0 * HIDDEN + out;
    const float* xpB = xpA + HIDDEN;
    const size_t S = (size_t)BB * HIDDEN;

    // 4-deep prefetch queues (TT >= 4)
    float xa0 = __ldg(xpA),         xb0 = __ldg(xpB);
    float xa1 = __ldg(xpA + S),     xb1 = __ldg(xpB + S);
    float xa2 = __ldg(xpA + 2 * S), xb2 = __ldg(xpB + 2 * S);
    float xa3 = __ldg(xpA + 3 * S), xb3 = __ldg(xpB + 3 * S);

    float hc0 = 0.f, hc1 = 0.f;

    #pragma unroll 2
    for (int t = 0; t < TT; ++t) {
        float na = 0.f, nb = 0.f;
        if (t + 4 < TT) {
            na = __ldg(xpA + (size_t)(t + 4) * S);
            nb = __ldg(xpB + (size_t)(t + 4) * S);
        }

        const ulonglong2* hA = (const ulonglong2*)(s_h + (t & 1) * 256);
        const ulonglong2* hB = (const ulonglong2*)(s_h + (t & 1) * 256 + 128);

        unsigned long long a[8], bq[8];
        #pragma unroll
        for (int i = 0; i < 8; ++i) { a[i] = 0ull; bq[i] = 0ull; }

        #pragma unroll
        for (int k = 0; k < 32; ++k) {       // 32 x 16B = 128 floats
            ulonglong2 u = hA[k];            // broadcast: 1 wavefront
            ulonglong2 v = hB[k];
            const int s = (k & 3) * 2;
            a[s]      = fma2(wh[2 * k],     u.x, a[s]);
            a[s + 1]  = fma2(wh[2 * k + 1], u.y, a[s + 1]);
            bq[s]     = fma2(wh[2 * k],     v.x, bq[s]);
            bq[s + 1] = fma2(wh[2 * k + 1], v.y, bq[s + 1]);
        }
        // packed-add reduce trees
        unsigned long long ra = add2(add2(a[0], a[1]), add2(a[2], a[3]));
        ra = add2(ra, add2(add2(a[4], a[5]), add2(a[6], a[7])));
        unsigned long long rb = add2(add2(bq[0], bq[1]), add2(bq[2], bq[3]));
        rb = add2(rb, add2(add2(bq[4], bq[5]), add2(bq[6], bq[7])));
        float2 fa = unpack2(ra), fb = unpack2(rb);

        hc0 = fast_tanh(fa.x + fa.y + xa0);
        hc1 = fast_tanh(fb.x + fb.y + xb0);

        float* hn = s_h + ((t + 1) & 1) * 256;
        hn[out]       = hc0;
        hn[128 + out] = hc1;

        xa0 = xa1; xa1 = xa2; xa2 = xa3; xa3 = na;
        xb0 = xb1; xb1 = xb2; xb2 = xb3; xb3 = nb;
        __syncthreads();
    }

    // final hidden (TT even -> lives in buffer 0, already synced)
    out_hidden[(size_t)b0 * HIDDEN + out]       = hc0;
    out_hidden[(size_t)(b0 + 1) * HIDDEN + out] = hc1;

    // ---- fused MLP head for rows b0, b0+1 ----
    const float* hfin = s_h;             // [2][128], buffer 0
    #pragma unroll
    for (int part = 0; part < 2; ++part) {
        const int m = out + part * 128;  // mlp output index 0..255
        const float4* w4 = (const float4*)(W1 + (size_t)m * HIDDEN);
        float acc0 = b1[m], acc1 = acc0;
        const float4* h40 = (const float4*)(hfin);
        const float4* h41 = (const float4*)(hfin + 128);
        #pragma unroll 8
        for (int k4 = 0; k4 < 32; ++k4) {
            float4 w = __ldg(&w4[k4]);
            float4 u = h40[k4];
            float4 v = h41[k4];
            acc0 = fmaf(w.x, u.x, acc0); acc0 = fmaf(w.y, u.y, acc0);
            acc0 = fmaf(w.z, u.z, acc0); acc0 = fmaf(w.w, u.w, acc0);
            acc1 = fmaf(w.x, v.x, acc1); acc1 = fmaf(w.y, v.y, acc1);
            acc1 = fmaf(w.z, v.z, acc1); acc1 = fmaf(w.w, v.w, acc1);
        }
        s_mlp[m]       = fmaxf(acc0, 0.0f);
        s_mlp[256 + m] = fmaxf(acc1, 0.0f);
    }
    __syncthreads();

    if (out < 8) {
        const int row = out >> 2, cls = out & 3;
        const float* mv = s_mlp + row * 256;
        const float* w2 = W2 + (size_t)cls * (2 * HIDDEN);
        float acc = b2[cls];
        #pragma unroll 8
        for (int k = 0; k < 256; ++k)
            acc = fmaf(mv[k], __ldg(&w2[k]), acc);
        logits[(size_t)(b0 + row) * NCLASS + cls] = acc;
    }
}

// ---------------------------------------------------------------------------
extern "C" void kernel_launch(void* const* d_in, const int* in_sizes, int n_in,
                              void* d_out, int out_size)
{
    const int*   x    = (const int*)  d_in[0];
    const float* h0   = (const float*)d_in[1];
    const float* emb  = (const float*)d_in[2];
    const float* W_ih = (const float*)d_in[3];
    const float* W_hh = (const float*)d_in[4];
    const float* b_ih = (const float*)d_in[5];
    const float* b_hh = (const float*)d_in[6];
    const float* W1   = (const float*)d_in[7];
    const float* b1   = (const float*)d_in[8];
    const float* W2   = (const float*)d_in[9];
    const float* b2   = (const float*)d_in[10];

    float* out    = (float*)d_out;
    float* logits = out;                 // [256*4]
    float* hidden = out + BB * NCLASS;   // [256*128]

    const int smem1 = XPS_TOT * sizeof(float);   // ~20KB
    const int smem2 = RH_TOT * sizeof(float);    // 20KB

    xproj_kernel<<<XP_GRID, 512, smem1>>>(x, emb, W_ih, b_ih, b_hh);
    rnn_head_kernel<<<BB / 2, 128, smem2>>>(h0, W_hh, W1, b1, W2, b2,
                                            logits, hidden);
}

// round 11
// speedup vs baseline: 1.2197x; 1.0226x over previous
#include <cuda_runtime.h>
#include <math.h>

#define VOCAB   50257
#define EMBED   128
#define HIDDEN  128
#define NCLASS  4
#define BB      256
#define TT      512
#define NTOK    (BB * TT)

// x_proj scratch [t][b][h] : 64MB device global (no runtime alloc)
__device__ float g_xp[TT * BB * HIDDEN];

// ---------------------------------------------------------------- helpers
__device__ __forceinline__ unsigned smem_u32(const void* p) {
    return (unsigned)__cvta_generic_to_shared(p);
}
__device__ __forceinline__ void cp_async16(void* dst, const void* src) {
    asm volatile("cp.async.cg.shared.global [%0], [%1], 16;"
                 :: "r"(smem_u32(dst)), "l"(src));
}
__device__ __forceinline__ void cp_commit() {
    asm volatile("cp.async.commit_group;");
}
__device__ __forceinline__ void cp_wait1() {
    asm volatile("cp.async.wait_group 1;");
}
__device__ __forceinline__ void cp_wait0() {
    asm volatile("cp.async.wait_group 0;");
}
#define NBAR_SYNC(id, cnt) \
    asm volatile("bar.sync %0, %1;" :: "r"(id), "r"(cnt) : "memory")

// packed dual fp32 ops (sm_103a f32x2 pipe)
__device__ __forceinline__ unsigned long long
fma2(unsigned long long a, unsigned long long b, unsigned long long c) {
    unsigned long long d;
    asm("fma.rn.f32x2 %0, %1, %2, %3;" : "=l"(d) : "l"(a), "l"(b), "l"(c));
    return d;
}
__device__ __forceinline__ unsigned long long
add2(unsigned long long a, unsigned long long b) {
    unsigned long long d;
    asm("add.rn.f32x2 %0, %1, %2;" : "=l"(d) : "l"(a), "l"(b));
    return d;
}
__device__ __forceinline__ float2 unpack2(unsigned long long v) {
    float2 r;
    asm("mov.b64 {%0, %1}, %2;" : "=f"(r.x), "=f"(r.y) : "l"(v));
    return r;
}
__device__ __forceinline__ float fast_tanh(float x) {
    x = fminf(fmaxf(x, -15.0f), 15.0f);
    float e = __expf(2.0f * x);
    return 1.0f - __fdividef(2.0f, e + 1.0f);
}

// ---------------------------------------------------------------------------
// Kernel 1 (proven round-6 version, 152us): x_proj = emb[x] @ W_ih^T + bias
// ---------------------------------------------------------------------------
#define XP_GRID  148
#define XP_TPC   886
#define XP_CH    16
#define XP_NC    ((XP_TPC + XP_CH - 1) / XP_CH)   // 56

#define XPS_IDS   0
#define XPS_ACT   896
#define XPS_TOT   (896 + 4096)

__device__ __forceinline__ float2 dot32x2(
    const ulonglong2* __restrict__ srcq,
    const unsigned long long* __restrict__ wA,
    const unsigned long long* __restrict__ wB)
{
    unsigned long long a0 = 0, a1 = 0, b0 = 0, b1 = 0;
    #pragma unroll
    for (int j = 0; j < 8; ++j) {
        ulonglong2 v = srcq[j * 4];
        a0 = fma2(wA[2 * j],     v.x, a0);
        a1 = fma2(wA[2 * j + 1], v.y, a1);
        b0 = fma2(wB[2 * j],     v.x, b0);
        b1 = fma2(wB[2 * j + 1], v.y, b1);
    }
    float2 ua0 = unpack2(a0), ua1 = unpack2(a1);
    float2 ub0 = unpack2(b0), ub1 = unpack2(b1);
    float d0 = (ua0.x + ua0.y) + (ua1.x + ua1.y);
    float d1 = (ub0.x + ub0.y) + (ub1.x + ub1.y);
    d0 += __shfl_xor_sync(0xffffffffu, d0, 8);
    d0 += __shfl_xor_sync(0xffffffffu, d0, 16);
    d1 += __shfl_xor_sync(0xffffffffu, d1, 8);
    d1 += __shfl_xor_sync(0xffffffffu, d1, 16);
    return make_float2(d0, d1);
}

__device__ __forceinline__ void load_wslice(
    const float* __restrict__ s_stg, int o0, int q,
    unsigned long long* __restrict__ wA, unsigned long long* __restrict__ wB)
{
    const unsigned long long* rA =
        (const unsigned long long*)(s_stg + (o0 & 31) * 128 + q * 32);
    const unsigned long long* rB =
        (const unsigned long long*)(s_stg + ((o0 & 31) + 1) * 128 + q * 32);
    #pragma unroll
    for (int k = 0; k < 16; ++k) { wA[k] = rA[k]; wB[k] = rB[k]; }
}

__global__ void __launch_bounds__(512, 1) xproj_kernel(
    const int* __restrict__ x, const float* __restrict__ emb,
    const float* __restrict__ W_ih, const float* __restrict__ b_ih,
    const float* __restrict__ b_hh)
{
    extern __shared__ float sh[];
    int*   s_ids = (int*)(sh + XPS_IDS);
    float* s_act = sh + XPS_ACT;

    const int tid  = threadIdx.x;
    const int lane = tid & 31;
    const int wid  = tid >> 5;
    const int oid  = lane & 7;
    const int q    = lane >> 3;
    const int o0   = ((wid & 7) << 4) + oid * 2;
    const int sub  = wid >> 3;
    const int r0   = blockIdx.x * XP_TPC;

    for (int i = tid; i < 896; i += 512) {
        int r = r0 + i;
        s_ids[i] = (i < XP_TPC && r < NTOK) ? x[r] : 0;
    }

    unsigned long long wA[16], wB[16];
    for (int p = 0; p < 4; ++p) {
        for (int i = tid; i < 4096; i += 512)
            s_act[i] = W_ih[p * 4096 + i];
        __syncthreads();
        if ((o0 >> 5) == p) load_wslice(s_act, o0, q, wA, wB);
        __syncthreads();
    }
    const float bias0 = b_ih[o0] + b_hh[o0];
    const float bias1 = b_ih[o0 + 1] + b_hh[o0 + 1];

    const int st_slot = tid >> 5;
    const int st_k4   = tid & 31;
    const int st_dst  = st_slot * 128 + (st_k4 & 7) * 16 + (st_k4 >> 3) * 4;
    const int st_src  = st_k4 * 4;

    {
        int id = s_ids[st_slot];
        cp_async16(s_act + st_dst, emb + (size_t)id * EMBED + st_src);
        cp_commit();
    }

    for (int c = 0; c < XP_NC; ++c) {
        if (c + 1 < XP_NC) {
            float* dst = s_act + ((c + 1) & 1) * 2048;
            int id = s_ids[(c + 1) * XP_CH + st_slot];
            cp_async16(dst + st_dst, emb + (size_t)id * EMBED + st_src);
            cp_commit();
            cp_wait1();
        } else {
            cp_wait0();
        }
        __syncthreads();

        const float* buf = s_act + (c & 1) * 2048;
        #pragma unroll 2
        for (int j = 0; j < 8; ++j) {
            int slot = sub * 8 + j;
            const ulonglong2* srcq =
                (const ulonglong2*)(buf + slot * 128) + q;
            float2 d = dot32x2(srcq, wA, wB);
            int i_tok = c * XP_CH + slot;
            int r = r0 + i_tok;
            if (q == 0 && i_tok < XP_TPC && r < NTOK) {
                int b = r >> 9, t = r & (TT - 1);
                float2 v = make_float2(d.x + bias0, d.y + bias1);
                *(float2*)(g_xp + ((size_t)t * BB + b) * HIDDEN + o0) = v;
            }
        }
        __syncthreads();
    }
}

// ---------------------------------------------------------------------------
// Kernel 2: recurrence + fused MLP head. 128 CTAs x 256 threads (1 CTA/SM).
// CTA owns 2 batch rows; row = tid>>7 (warps 0-3 row 0, warps 4-7 row 1 —
// each SMSP hosts one warp of EACH row). Each row group syncs on its OWN
// named barrier -> the two rows run phase-decoupled; when one row stalls
// (barrier/tanh/LDS) the other row's warp on the same SMSP issues.
// Thread owns one output with the full 128-float W_hh row in registers.
// ---------------------------------------------------------------------------
// shared floats: h[2 bufs][2 rows][128] | mlp[2][256] | stage[4096]
#define RH_H    0
#define RH_MLP  512
#define RH_STG  1024
#define RH_TOT  (1024 + 4096)

__global__ void __launch_bounds__(256, 1) rnn_head_kernel(
    const float* __restrict__ h0, const float* __restrict__ W_hh,
    const float* __restrict__ W1, const float* __restrict__ b1,
    const float* __restrict__ W2, const float* __restrict__ b2,
    float* __restrict__ logits, float* __restrict__ out_hidden)
{
    extern __shared__ float sh[];
    float* s_h   = sh + RH_H;
    float* s_mlp = sh + RH_MLP;
    float* s_stg = sh + RH_STG;

    const int tid = threadIdx.x;
    const int out = tid & 127;
    const int row = tid >> 7;            // 0 or 1
    const int b   = blockIdx.x * 2 + row;

    // stage W_hh rows -> registers (2 coalesced passes, 256 threads)
    unsigned long long wh[64];
    for (int p = 0; p < 2; ++p) {
        for (int i = tid; i < 8192; i += 256)
            s_stg[i % 4096 + (i >> 12) * 0] = 0.0f;  // (placeholder no-op)
        // real staging: 64 rows per pass
        for (int i = tid; i < 4096; i += 256)
            s_stg[i] = W_hh[p * 8192 + i];
        __syncthreads();
        if ((out >> 5) == p * 2) {
            const unsigned long long* r =
                (const unsigned long long*)(s_stg + (out & 31) * 128);
            #pragma unroll
            for (int k = 0; k < 64; ++k) wh[k] = r[k];
        }
        __syncthreads();
        for (int i = tid; i < 4096; i += 256)
            s_stg[i] = W_hh[p * 8192 + 4096 + i];
        __syncthreads();
        if ((out >> 5) == p * 2 + 1) {
            const unsigned long long* r =
                (const unsigned long long*)(s_stg + (out & 31) * 128);
            #pragma unroll
            for (int k = 0; k < 64; ++k) wh[k] = r[k];
        }
        __syncthreads();
    }

    s_h[row * 128 + out] = h0[(size_t)b * HIDDEN + out];
    __syncthreads();

    const float* xp = g_xp + (size_t)b * HIDDEN + out;
    const size_t S = (size_t)BB * HIDDEN;

    // 4-deep prefetch queue
    float x0 = __ldg(xp);
    float x1 = __ldg(xp + S);
    float x2 = __ldg(xp + 2 * S);
    float x3 = __ldg(xp + 3 * S);

    const int bar = row + 1;             // named barrier id 1 / 2
    float hc = 0.f;

    for (int t = 0; t < TT; ++t) {
        float nx = (t + 4 < TT) ? __ldg(xp + (size_t)(t + 4) * S) : 0.f;

        const ulonglong2* hv =
            (const ulonglong2*)(s_h + (t & 1) * 256 + row * 128);

        unsigned long long a[8];
        #pragma unroll
        for (int i = 0; i < 8; ++i) a[i] = 0ull;

        #pragma unroll
        for (int k = 0; k < 32; ++k) {       // 32 x 16B = 128 floats
            ulonglong2 u = hv[k];            // broadcast: 1 wavefront
            const int s = (k & 3) * 2;
            a[s]     = fma2(wh[2 * k],     u.x, a[s]);
            a[s + 1] = fma2(wh[2 * k + 1], u.y, a[s + 1]);
        }
        unsigned long long ra = add2(add2(a[0], a[1]), add2(a[2], a[3]));
        ra = add2(ra, add2(add2(a[4], a[5]), add2(a[6], a[7])));
        float2 fa = unpack2(ra);

        hc = fast_tanh(fa.x + fa.y + x0);
        s_h[((t + 1) & 1) * 256 + row * 128 + out] = hc;

        x0 = x1; x1 = x2; x2 = x3; x3 = nx;
        NBAR_SYNC(bar, 128);                 // sync ONLY this row's 4 warps
    }

    out_hidden[(size_t)b * HIDDEN + out] = hc;

    // ---- fused MLP head (needs both rows' final h) ----
    __syncthreads();
    const float* hfin = s_h;             // buffer 0 (TT even), [2][128]
    {
        const int m = tid;               // 0..255 -> one W1 row, both batch rows
        const float4* w4 = (const float4*)(W1 + (size_t)m * HIDDEN);
        float acc0 = b1[m], acc1 = acc0;
        const float4* h40 = (const float4*)(hfin);
        const float4* h41 = (const float4*)(hfin + 128);
        #pragma unroll 8
        for (int k4 = 0; k4 < 32; ++k4) {
            float4 w = __ldg(&w4[k4]);
            float4 u = h40[k4];
            float4 v = h41[k4];
            acc0 = fmaf(w.x, u.x, acc0); acc0 = fmaf(w.y, u.y, acc0);
            acc0 = fmaf(w.z, u.z, acc0); acc0 = fmaf(w.w, u.w, acc0);
            acc1 = fmaf(w.x, v.x, acc1); acc1 = fmaf(w.y, v.y, acc1);
            acc1 = fmaf(w.z, v.z, acc1); acc1 = fmaf(w.w, v.w, acc1);
        }
        s_mlp[m]       = fmaxf(acc0, 0.0f);
        s_mlp[256 + m] = fmaxf(acc1, 0.0f);
    }
    __syncthreads();

    if (tid < 8) {
        const int r = tid >> 2, cls = tid & 3;
        const float* mv = s_mlp + r * 256;
        const float* w2 = W2 + (size_t)cls * (2 * HIDDEN);
        float acc = b2[cls];
        #pragma unroll 8
        for (int k = 0; k < 256; ++k)
            acc = fmaf(mv[k], __ldg(&w2[k]), acc);
        logits[(size_t)(blockIdx.x * 2 + r) * NCLASS + cls] = acc;
    }
}

// ---------------------------------------------------------------------------
extern "C" void kernel_launch(void* const* d_in, const int* in_sizes, int n_in,
                              void* d_out, int out_size)
{
    const int*   x    = (const int*)  d_in[0];
    const float* h0   = (const float*)d_in[1];
    const float* emb  = (const float*)d_in[2];
    const float* W_ih = (const float*)d_in[3];
    const float* W_hh = (const float*)d_in[4];
    const float* b_ih = (const float*)d_in[5];
    const float* b_hh = (const float*)d_in[6];
    const float* W1   = (const float*)d_in[7];
    const float* b1   = (const float*)d_in[8];
    const float* W2   = (const float*)d_in[9];
    const float* b2   = (const float*)d_in[10];

    float* out    = (float*)d_out;
    float* logits = out;                 // [256*4]
    float* hidden = out + BB * NCLASS;   // [256*128]

    const int smem1 = XPS_TOT * sizeof(float);   // ~20KB
    const int smem2 = RH_TOT * sizeof(float);    // 20KB

    xproj_kernel<<<XP_GRID, 512, smem1>>>(x, emb, W_ih, b_ih, b_hh);
    rnn_head_kernel<<<BB / 2, 256, smem2>>>(h0, W_hh, W1, b1, W2, b2,
                                            logits, hidden);
}

// round 12
// speedup vs baseline: 1.2887x; 1.0566x over previous
#include <cuda_runtime.h>
#include <math.h>

#define HIDDEN  128
#define NCLASS  4
#define BB      256
#define TT      512
#define NBATCH  (TT / 4)     // 128 four-token batches

// ---------------------------------------------------------------- helpers
__device__ __forceinline__ unsigned smem_u32(const void* p) {
    return (unsigned)__cvta_generic_to_shared(p);
}
__device__ __forceinline__ void cp_async16(void* dst, const void* src) {
    asm volatile("cp.async.cg.shared.global [%0], [%1], 16;"
                 :: "r"(smem_u32(dst)), "l"(src));
}
__device__ __forceinline__ void cp_commit() {
    asm volatile("cp.async.commit_group;");
}
__device__ __forceinline__ void cp_wait1() {
    asm volatile("cp.async.wait_group 1;");
}
__device__ __forceinline__ void cp_wait0() {
    asm volatile("cp.async.wait_group 0;");
}
#define BAR_SYNC(id, cnt) \
    asm volatile("bar.sync %0, %1;" :: "r"(id), "r"(cnt) : "memory")
#define BAR_ARRIVE(id, cnt) \
    asm volatile("bar.arrive %0, %1;" :: "r"(id), "r"(cnt) : "memory")

__device__ __forceinline__ unsigned long long
fma2(unsigned long long a, unsigned long long b, unsigned long long c) {
    unsigned long long d;
    asm("fma.rn.f32x2 %0, %1, %2, %3;" : "=l"(d) : "l"(a), "l"(b), "l"(c));
    return d;
}
__device__ __forceinline__ unsigned long long
add2(unsigned long long a, unsigned long long b) {
    unsigned long long d;
    asm("add.rn.f32x2 %0, %1, %2;" : "=l"(d) : "l"(a), "l"(b));
    return d;
}
__device__ __forceinline__ float2 unpack2(unsigned long long v) {
    float2 r;
    asm("mov.b64 {%0, %1}, %2;" : "=f"(r.x), "=f"(r.y) : "l"(v));
    return r;
}
__device__ __forceinline__ float fast_tanh(float x) {
    x = fminf(fmaxf(x, -15.0f), 15.0f);
    float e = __expf(2.0f * x);
    return 1.0f - __fdividef(2.0f, e + 1.0f);
}

// ---------------------------------------------------------------------------
// Shared layout (float offsets)
//   ids  [2 rows][512]                (ints)          1024
//   emb  [2 bufs][4 tok][2 rows][128]                 2048
//   xp   [2 bufs][4 tok][2 rows][128]                 2048
//   h    [2 bufs][2 rows][128]                         512
//   mlp  [2 rows][256]                                 512
//   stg  weight staging                               4096
// ---------------------------------------------------------------------------
#define SH_IDS  0
#define SH_EMB  1024
#define SH_XP   (1024 + 2048)
#define SH_H    (1024 + 2048 + 2048)
#define SH_MLP  (SH_H + 512)
#define SH_STG  (SH_MLP + 512)
#define SH_TOT  (SH_STG + 4096)      // 10240 floats = 40KB

// Barrier ids: 1,2 = row bars; 3 = producer-internal;
//              4,5 = full[buf]; 6,7 = empty[buf]. (0 = __syncthreads)

__global__ void __launch_bounds__(384, 1) fused_kernel(
    const int* __restrict__ x, const float* __restrict__ emb,
    const float* __restrict__ W_ih, const float* __restrict__ W_hh,
    const float* __restrict__ b_ih, const float* __restrict__ b_hh,
    const float* __restrict__ h0,
    const float* __restrict__ W1, const float* __restrict__ b1,
    const float* __restrict__ W2, const float* __restrict__ b2,
    float* __restrict__ logits, float* __restrict__ out_hidden)
{
    extern __shared__ float sh[];
    int*   s_ids = (int*)(sh + SH_IDS);
    float* s_emb = sh + SH_EMB;
    float* s_xp  = sh + SH_XP;
    float* s_h   = sh + SH_H;
    float* s_mlp = sh + SH_MLP;
    float* s_stg = sh + SH_STG;

    const int tid = threadIdx.x;
    const int b0  = blockIdx.x * 2;
    const bool is_prod = (tid >= 256);      // warps 8-11
    const int  myout   = is_prod ? (tid - 256) : (tid & 127);

    // ---- stage token ids for both rows
    for (int i = tid; i < 2 * TT; i += 384) {
        int row = i >> 9, t = i & 511;
        s_ids[i] = x[(size_t)(b0 + row) * TT + t];
    }

    // ---- load weights into registers:
    //      consumers get W_hh[myout][*], producers get W_ih[myout][*]
    unsigned long long wreg[64];
    for (int p = 0; p < 4; ++p) {
        for (int i = tid; i < 4096; i += 384)
            s_stg[i] = W_hh[p * 4096 + i];
        __syncthreads();
        if (!is_prod && (myout >> 5) == p) {
            const unsigned long long* r =
                (const unsigned long long*)(s_stg + (myout & 31) * 128);
            #pragma unroll
            for (int k = 0; k < 64; ++k) wreg[k] = r[k];
        }
        __syncthreads();
    }
    for (int p = 0; p < 4; ++p) {
        for (int i = tid; i < 4096; i += 384)
            s_stg[i] = W_ih[p * 4096 + i];
        __syncthreads();
        if (is_prod && (myout >> 5) == p) {
            const unsigned long long* r =
                (const unsigned long long*)(s_stg + (myout & 31) * 128);
            #pragma unroll
            for (int k = 0; k < 64; ++k) wreg[k] = r[k];
        }
        __syncthreads();
    }
    const float bias = b_ih[myout] + b_hh[myout];

    // ---- init h buffer 0
    if (!is_prod) {
        int row = tid >> 7;
        s_h[row * 128 + myout] = h0[(size_t)(b0 + row) * HIDDEN + myout];
    }
    __syncthreads();

    if (is_prod) {
        // ================= PRODUCER: xp[t] = emb[x[b,t]] . W_ih[out] + bias
        const int p = tid - 256;      // 0..127

        // prologue: stage emb batch 0 into buf 0
        #pragma unroll
        for (int cc = 0; cc < 2; ++cc) {
            int c = p + cc * 128;
            int j = c >> 6, row = (c >> 5) & 1, part = c & 31;
            int id = s_ids[row * TT + 0 + j];
            cp_async16(s_emb + 0 * 1024 + j * 256 + row * 128 + part * 4,
                       emb + (size_t)id * HIDDEN + part * 4);
        }
        cp_commit();

        for (int bb = 0; bb < NBATCH; ++bb) {
            const int buf = bb & 1;
            if (bb >= 2) BAR_SYNC(6 + buf, 384);        // wait slot empty

            if (bb + 1 < NBATCH) {                      // stage batch bb+1
                const int nb = buf ^ 1, T = 4 * (bb + 1);
                #pragma unroll
                for (int cc = 0; cc < 2; ++cc) {
                    int c = p + cc * 128;
                    int j = c >> 6, row = (c >> 5) & 1, part = c & 31;
                    int id = s_ids[row * TT + T + j];
                    cp_async16(s_emb + nb * 1024 + j * 256 + row * 128 + part * 4,
                               emb + (size_t)id * HIDDEN + part * 4);
                }
                cp_commit();
                cp_wait1();                             // batch bb complete
            } else {
                cp_wait0();
            }
            BAR_SYNC(3, 128);                           // emb bb visible

            #pragma unroll
            for (int j = 0; j < 4; ++j) {
                #pragma unroll
                for (int r = 0; r < 2; ++r) {
                    const ulonglong2* e = (const ulonglong2*)
                        (s_emb + buf * 1024 + j * 256 + r * 128);
                    unsigned long long a0 = 0, a1 = 0, a2 = 0, a3 = 0;
                    #pragma unroll
                    for (int k = 0; k < 32; ++k) {
                        ulonglong2 v = e[k];            // broadcast LDS
                        if (k & 1) {
                            a2 = fma2(wreg[2 * k],     v.x, a2);
                            a3 = fma2(wreg[2 * k + 1], v.y, a3);
                        } else {
                            a0 = fma2(wreg[2 * k],     v.x, a0);
                            a1 = fma2(wreg[2 * k + 1], v.y, a1);
                        }
                    }
                    float2 u = unpack2(add2(add2(a0, a1), add2(a2, a3)));
                    s_xp[buf * 1024 + j * 256 + r * 128 + myout] =
                        u.x + u.y + bias;
                }
            }
            BAR_ARRIVE(4 + buf, 384);                   // slot full
        }
    } else {
        // ================= CONSUMER: h[t+1] = tanh(W_hh h[t] + xp[t])
        const int row  = tid >> 7;
        const int rbar = 1 + row;
        float hc = 0.f;

        for (int bb = 0; bb < NBATCH; ++bb) {
            const int buf = bb & 1;
            BAR_SYNC(4 + buf, 384);                     // wait xp batch full
            #pragma unroll
            for (int j = 0; j < 4; ++j) {
                float xv = s_xp[buf * 1024 + j * 256 + row * 128 + myout];
                const ulonglong2* hv = (const ulonglong2*)
                    (s_h + (j & 1) * 256 + row * 128);

                unsigned long long a[8];
                #pragma unroll
                for (int i = 0; i < 8; ++i) a[i] = 0ull;
                #pragma unroll
                for (int k = 0; k < 32; ++k) {
                    ulonglong2 v = hv[k];               // broadcast LDS
                    const int s = (k & 3) * 2;
                    a[s]     = fma2(wreg[2 * k],     v.x, a[s]);
                    a[s + 1] = fma2(wreg[2 * k + 1], v.y, a[s + 1]);
                }
                unsigned long long ra =
                    add2(add2(a[0], a[1]), add2(a[2], a[3]));
                ra = add2(ra, add2(add2(a[4], a[5]), add2(a[6], a[7])));
                float2 fa = unpack2(ra);

                hc = fast_tanh(fa.x + fa.y + xv);
                s_h[((j + 1) & 1) * 256 + row * 128 + myout] = hc;
                BAR_SYNC(rbar, 128);                    // publish h (row only)
            }
            BAR_ARRIVE(6 + buf, 384);                   // slot consumed
        }
        out_hidden[(size_t)(b0 + row) * HIDDEN + myout] = hc;
    }

    // ================= fused MLP head (h final is in s_h buffer 0)
    __syncthreads();
    if (tid < 256) {
        const int m = tid;                // W1 row, evaluated for both batch rows
        const float4* w4 = (const float4*)(W1 + (size_t)m * HIDDEN);
        float acc0 = b1[m], acc1 = acc0;
        const float4* h40 = (const float4*)(s_h);
        const float4* h41 = (const float4*)(s_h + 128);
        #pragma unroll 8
        for (int k4 = 0; k4 < 32; ++k4) {
            float4 w = __ldg(&w4[k4]);
            float4 u = h40[k4];
            float4 v = h41[k4];
            acc0 = fmaf(w.x, u.x, acc0); acc0 = fmaf(w.y, u.y, acc0);
            acc0 = fmaf(w.z, u.z, acc0); acc0 = fmaf(w.w, u.w, acc0);
            acc1 = fmaf(w.x, v.x, acc1); acc1 = fmaf(w.y, v.y, acc1);
            acc1 = fmaf(w.z, v.z, acc1); acc1 = fmaf(w.w, v.w, acc1);
        }
        s_mlp[m]       = fmaxf(acc0, 0.0f);
        s_mlp[256 + m] = fmaxf(acc1, 0.0f);
    }
    __syncthreads();

    if (tid < 8) {
        const int r = tid >> 2, cls = tid & 3;
        const float* mv = s_mlp + r * 256;
        const float* w2 = W2 + (size_t)cls * (2 * HIDDEN);
        float acc = b2[cls];
        #pragma unroll 8
        for (int k = 0; k < 256; ++k)
            acc = fmaf(mv[k], __ldg(&w2[k]), acc);
        logits[(size_t)(b0 + r) * NCLASS + cls] = acc;
    }
}

// ---------------------------------------------------------------------------
extern "C" void kernel_launch(void* const* d_in, const int* in_sizes, int n_in,
                              void* d_out, int out_size)
{
    const int*   x    = (const int*)  d_in[0];
    const float* h0   = (const float*)d_in[1];
    const float* emb  = (const float*)d_in[2];
    const float* W_ih = (const float*)d_in[3];
    const float* W_hh = (const float*)d_in[4];
    const float* b_ih = (const float*)d_in[5];
    const float* b_hh = (const float*)d_in[6];
    const float* W1   = (const float*)d_in[7];
    const float* b1   = (const float*)d_in[8];
    const float* W2   = (const float*)d_in[9];
    const float* b2   = (const float*)d_in[10];

    float* out    = (float*)d_out;
    float* logits = out;                 // [256*4]
    float* hidden = out + BB * NCLASS;   // [256*128]

    const int smem = SH_TOT * sizeof(float);   // 40KB

    fused_kernel<<<BB / 2, 384, smem>>>(x, emb, W_ih, W_hh, b_ih, b_hh, h0,
                                        W1, b1, W2, b2, logits, hidden);
}

// round 14
// speedup vs baseline: 1.2994x; 1.0083x over previous
#include <cuda_runtime.h>
#include <math.h>

#define HIDDEN  128
#define NCLASS  4
#define BB      256
#define TT      512
#define NBATCH  (TT / 4)     // 128 four-token batches

// ---------------------------------------------------------------- helpers
__device__ __forceinline__ unsigned smem_u32(const void* p) {
    return (unsigned)__cvta_generic_to_shared(p);
}
__device__ __forceinline__ void cp_async16(void* dst, const void* src) {
    asm volatile("cp.async.cg.shared.global [%0], [%1], 16;"
                 :: "r"(smem_u32(dst)), "l"(src));
}
__device__ __forceinline__ void cp_commit() {
    asm volatile("cp.async.commit_group;");
}
__device__ __forceinline__ void cp_wait1() {
    asm volatile("cp.async.wait_group 1;");
}
__device__ __forceinline__ void cp_wait0() {
    asm volatile("cp.async.wait_group 0;");
}
#define BAR_SYNC(id, cnt) \
    asm volatile("bar.sync %0, %1;" :: "r"(id), "r"(cnt) : "memory")
#define BAR_ARRIVE(id, cnt) \
    asm volatile("bar.arrive %0, %1;" :: "r"(id), "r"(cnt) : "memory")

__device__ __forceinline__ unsigned long long
fma2(unsigned long long a, unsigned long long b, unsigned long long c) {
    unsigned long long d;
    asm("fma.rn.f32x2 %0, %1, %2, %3;" : "=l"(d) : "l"(a), "l"(b), "l"(c));
    return d;
}
__device__ __forceinline__ unsigned long long
add2(unsigned long long a, unsigned long long b) {
    unsigned long long d;
    asm("add.rn.f32x2 %0, %1, %2;" : "=l"(d) : "l"(a), "l"(b));
    return d;
}
__device__ __forceinline__ float2 unpack2(unsigned long long v) {
    float2 r;
    asm("mov.b64 {%0, %1}, %2;" : "=f"(r.x), "=f"(r.y) : "l"(v));
    return r;
}
__device__ __forceinline__ float fast_tanh(float x) {
    x = fminf(fmaxf(x, -15.0f), 15.0f);
    float e = __expf(2.0f * x);
    return 1.0f - __fdividef(2.0f, e + 1.0f);
}

// ---------------------------------------------------------------------------
// Shared layout (float offsets)
//   ids  [2 rows][512]  (ints)                        1024
//   emb  [2 bufs][4 tok][2 rows][128]                 2048
//   xp   [2 bufs][4 tok][2 rows][128]                 2048
//   h    [2 bufs][2 rows][128]                         512
//   mlp  [2 rows][256]                                 512
//   stg  weight staging                               4096
// ---------------------------------------------------------------------------
#define SH_IDS  0
#define SH_EMB  1024
#define SH_XP   (1024 + 2048)
#define SH_H    (1024 + 2048 + 2048)
#define SH_MLP  (SH_H + 512)
#define SH_STG  (SH_MLP + 512)
#define SH_TOT  (SH_STG + 4096)      // 10240 floats = 40KB

// Barrier ids:
//   0           __syncthreads (384)
//   1 + row     consumer row bar (128)
//   3           producer-internal emb-visibility bar (128)
//   4 + buf     full[row0][buf]  (256: 128 prod arrive, 128 cons sync)
//   6 + buf     full[row1][buf]
//   8 + buf     empty[row0][buf] (256: 128 cons arrive, 128 prod sync)
//  10 + buf     empty[row1][buf]

__global__ void __launch_bounds__(384, 1) fused_kernel(
    const int* __restrict__ x, const float* __restrict__ emb,
    const float* __restrict__ W_ih, const float* __restrict__ W_hh,
    const float* __restrict__ b_ih, const float* __restrict__ b_hh,
    const float* __restrict__ h0,
    const float* __restrict__ W1, const float* __restrict__ b1,
    const float* __restrict__ W2, const float* __restrict__ b2,
    float* __restrict__ logits, float* __restrict__ out_hidden)
{
    extern __shared__ float sh[];
    int*   s_ids = (int*)(sh + SH_IDS);
    float* s_emb = sh + SH_EMB;
    float* s_xp  = sh + SH_XP;
    float* s_h   = sh + SH_H;
    float* s_mlp = sh + SH_MLP;
    float* s_stg = sh + SH_STG;

    const int tid = threadIdx.x;
    const int b0  = blockIdx.x * 2;
    const bool is_prod = (tid >= 256);      // warps 8-11
    const int  myout   = is_prod ? (tid - 256) : (tid & 127);

    // ---- stage token ids for both rows
    for (int i = tid; i < 2 * TT; i += 384) {
        int row = i >> 9, t = i & 511;
        s_ids[i] = x[(size_t)(b0 + row) * TT + t];
    }

    // ---- load weights into registers:
    //      consumers get W_hh[myout][*], producers get W_ih[myout][*]
    unsigned long long wreg[64];
    for (int p = 0; p < 4; ++p) {
        for (int i = tid; i < 4096; i += 384)
            s_stg[i] = W_hh[p * 4096 + i];
        __syncthreads();
        if (!is_prod && (myout >> 5) == p) {
            const unsigned long long* r =
                (const unsigned long long*)(s_stg + (myout & 31) * 128);
            #pragma unroll
            for (int k = 0; k < 64; ++k) wreg[k] = r[k];
        }
        __syncthreads();
    }
    for (int p = 0; p < 4; ++p) {
        for (int i = tid; i < 4096; i += 384)
            s_stg[i] = W_ih[p * 4096 + i];
        __syncthreads();
        if (is_prod && (myout >> 5) == p) {
            const unsigned long long* r =
                (const unsigned long long*)(s_stg + (myout & 31) * 128);
            #pragma unroll
            for (int k = 0; k < 64; ++k) wreg[k] = r[k];
        }
        __syncthreads();
    }
    const float bias = b_ih[myout] + b_hh[myout];

    // ---- init h buffer 0
    if (!is_prod) {
        int row = tid >> 7;
        s_h[row * 128 + myout] = h0[(size_t)(b0 + row) * HIDDEN + myout];
    }
    __syncthreads();

    if (is_prod) {
        // ============ PRODUCER (proven R12 structure): thread owns one W_ih
        // row, computes xp for all 8 (token,row) pairs of each 4-token batch.
        const int p = tid - 256;      // 0..127

        // prologue: stage emb batch 0 into buf 0 (cooperative, 128 threads)
        #pragma unroll
        for (int cc = 0; cc < 2; ++cc) {
            int c = p + cc * 128;
            int j = c >> 6, row = (c >> 5) & 1, part = c & 31;
            int id = s_ids[row * TT + 0 + j];
            cp_async16(s_emb + 0 * 1024 + j * 256 + row * 128 + part * 4,
                       emb + (size_t)id * HIDDEN + part * 4);
        }
        cp_commit();

        for (int bb = 0; bb < NBATCH; ++bb) {
            const int buf = bb & 1;
            if (bb >= 2) {                               // xp slot empty?
                BAR_SYNC(8 + buf, 256);                  // row 0 consumed
                BAR_SYNC(10 + buf, 256);                 // row 1 consumed
            }

            if (bb + 1 < NBATCH) {                       // stage batch bb+1
                const int nb = buf ^ 1, T = 4 * (bb + 1);
                #pragma unroll
                for (int cc = 0; cc < 2; ++cc) {
                    int c = p + cc * 128;
                    int j = c >> 6, row = (c >> 5) & 1, part = c & 31;
                    int id = s_ids[row * TT + T + j];
                    cp_async16(s_emb + nb * 1024 + j * 256 + row * 128 + part * 4,
                               emb + (size_t)id * HIDDEN + part * 4);
                }
                cp_commit();
                cp_wait1();                              // batch bb complete
            } else {
                cp_wait0();
            }
            BAR_SYNC(3, 128);                            // emb bb visible

            #pragma unroll
            for (int j = 0; j < 4; ++j) {
                #pragma unroll
                for (int r = 0; r < 2; ++r) {
                    const ulonglong2* e = (const ulonglong2*)
                        (s_emb + buf * 1024 + j * 256 + r * 128);
                    unsigned long long a0 = 0, a1 = 0, a2 = 0, a3 = 0;
                    #pragma unroll
                    for (int k = 0; k < 32; ++k) {
                        ulonglong2 v = e[k];             // broadcast LDS
                        if (k & 1) {
                            a2 = fma2(wreg[2 * k],     v.x, a2);
                            a3 = fma2(wreg[2 * k + 1], v.y, a3);
                        } else {
                            a0 = fma2(wreg[2 * k],     v.x, a0);
                            a1 = fma2(wreg[2 * k + 1], v.y, a1);
                        }
                    }
                    float2 u = unpack2(add2(add2(a0, a1), add2(a2, a3)));
                    s_xp[buf * 1024 + j * 256 + r * 128 + myout] =
                        u.x + u.y + bias;
                }
            }
            BAR_ARRIVE(4 + buf, 256);                    // row 0 slot full
            BAR_ARRIVE(6 + buf, 256);                    // row 1 slot full
        }
    } else {
        // ============ CONSUMER: h[t+1] = tanh(W_hh h[t] + xp[t]).
        // Row-private full/empty handshakes: rows drift independently.
        const int row  = tid >> 7;
        const int rbar = 1 + row;
        const int fullb  = 4 + row * 2;                  // 4/5 or 6/7
        const int emptyb = 8 + row * 2;                  // 8/9 or 10/11
        float hc = 0.f;

        for (int bb = 0; bb < NBATCH; ++bb) {
            const int buf = bb & 1;
            BAR_SYNC(fullb + buf, 256);                  // my row's xp ready

            float xv[4];
            #pragma unroll
            for (int j = 0; j < 4; ++j)
                xv[j] = s_xp[buf * 1024 + j * 256 + row * 128 + myout];

            #pragma unroll
            for (int j = 0; j < 4; ++j) {
                const ulonglong2* hv = (const ulonglong2*)
                    (s_h + (j & 1) * 256 + row * 128);

                unsigned long long a[8];
                #pragma unroll
                for (int i = 0; i < 8; ++i) a[i] = 0ull;
                #pragma unroll
                for (int k = 0; k < 32; ++k) {
                    ulonglong2 v = hv[k];                // broadcast LDS
                    const int s = (k & 3) * 2;
                    a[s]     = fma2(wreg[2 * k],     v.x, a[s]);
                    a[s + 1] = fma2(wreg[2 * k + 1], v.y, a[s + 1]);
                }
                unsigned long long ra =
                    add2(add2(a[0], a[1]), add2(a[2], a[3]));
                ra = add2(ra, add2(add2(a[4], a[5]), add2(a[6], a[7])));
                float2 fa = unpack2(ra);

                hc = fast_tanh(fa.x + fa.y + xv[j]);
                s_h[((j + 1) & 1) * 256 + row * 128 + myout] = hc;
                BAR_SYNC(rbar, 128);                     // publish h (row scope)
            }
            BAR_ARRIVE(emptyb + buf, 256);               // my row consumed
        }
        out_hidden[(size_t)(b0 + row) * HIDDEN + myout] = hc;
    }

    // ============ fused MLP head (final h is in s_h buffer 0)
    __syncthreads();
    if (tid < 256) {
        const int m = tid;
        const float4* w4 = (const float4*)(W1 + (size_t)m * HIDDEN);
        float acc0 = b1[m], acc1 = acc0;
        const float4* h40 = (const float4*)(s_h);
        const float4* h41 = (const float4*)(s_h + 128);
        #pragma unroll 8
        for (int k4 = 0; k4 < 32; ++k4) {
            float4 w = __ldg(&w4[k4]);
            float4 u = h40[k4];
            float4 v = h41[k4];
            acc0 = fmaf(w.x, u.x, acc0); acc0 = fmaf(w.y, u.y, acc0);
            acc0 = fmaf(w.z, u.z, acc0); acc0 = fmaf(w.w, u.w, acc0);
            acc1 = fmaf(w.x, v.x, acc1); acc1 = fmaf(w.y, v.y, acc1);
            acc1 = fmaf(w.z, v.z, acc1); acc1 = fmaf(w.w, v.w, acc1);
        }
        s_mlp[m]       = fmaxf(acc0, 0.0f);
        s_mlp[256 + m] = fmaxf(acc1, 0.0f);
    }
    __syncthreads();

    if (tid < 8) {
        const int r = tid >> 2, cls = tid & 3;
        const float* mv = s_mlp + r * 256;
        const float* w2 = W2 + (size_t)cls * (2 * HIDDEN);
        float acc = b2[cls];
        #pragma unroll 8
        for (int k = 0; k < 256; ++k)
            acc = fmaf(mv[k], __ldg(&w2[k]), acc);
        logits[(size_t)(b0 + r) * NCLASS + cls] = acc;
    }
}

// ---------------------------------------------------------------------------
extern "C" void kernel_launch(void* const* d_in, const int* in_sizes, int n_in,
                              void* d_out, int out_size)
{
    const int*   x    = (const int*)  d_in[0];
    const float* h0   = (const float*)d_in[1];
    const float* emb  = (const float*)d_in[2];
    const float* W_ih = (const float*)d_in[3];
    const float* W_hh = (const float*)d_in[4];
    const float* b_ih = (const float*)d_in[5];
    const float* b_hh = (const float*)d_in[6];
    const float* W1   = (const float*)d_in[7];
    const float* b1   = (const float*)d_in[8];
    const float* W2   = (const float*)d_in[9];
    const float* b2   = (const float*)d_in[10];

    float* out    = (float*)d_out;
    float* logits = out;                 // [256*4]
    float* hidden = out + BB * NCLASS;   // [256*128]

    const int smem = SH_TOT * sizeof(float);   // 40KB

    fused_kernel<<<BB / 2, 384, smem>>>(x, emb, W_ih, W_hh, b_ih, b_hh, h0,
                                        W1, b1, W2, b2, logits, hidden);
}

// round 15
// speedup vs baseline: 1.3407x; 1.0318x over previous
#include <cuda_runtime.h>
#include <math.h>

#define HIDDEN  128
#define NCLASS  4
#define BB      256
#define TT      512
#define NBATCH  (TT / 4)     // 128 four-token batches

// ---------------------------------------------------------------- helpers
__device__ __forceinline__ unsigned smem_u32(const void* p) {
    return (unsigned)__cvta_generic_to_shared(p);
}
__device__ __forceinline__ void cp_async16(void* dst, const void* src) {
    asm volatile("cp.async.cg.shared.global [%0], [%1], 16;"
                 :: "r"(smem_u32(dst)), "l"(src));
}
__device__ __forceinline__ void cp_commit() {
    asm volatile("cp.async.commit_group;");
}
__device__ __forceinline__ void cp_wait1() {
    asm volatile("cp.async.wait_group 1;");
}
__device__ __forceinline__ void cp_wait0() {
    asm volatile("cp.async.wait_group 0;");
}
#define BAR_SYNC(id, cnt) \
    asm volatile("bar.sync %0, %1;" :: "r"(id), "r"(cnt) : "memory")
#define BAR_ARRIVE(id, cnt) \
    asm volatile("bar.arrive %0, %1;" :: "r"(id), "r"(cnt) : "memory")

__device__ __forceinline__ unsigned long long
fma2(unsigned long long a, unsigned long long b, unsigned long long c) {
    unsigned long long d;
    asm("fma.rn.f32x2 %0, %1, %2, %3;" : "=l"(d) : "l"(a), "l"(b), "l"(c));
    return d;
}
__device__ __forceinline__ unsigned long long
add2(unsigned long long a, unsigned long long b) {
    unsigned long long d;
    asm("add.rn.f32x2 %0, %1, %2;" : "=l"(d) : "l"(a), "l"(b));
    return d;
}
__device__ __forceinline__ float2 unpack2(unsigned long long v) {
    float2 r;
    asm("mov.b64 {%0, %1}, %2;" : "=f"(r.x), "=f"(r.y) : "l"(v));
    return r;
}
__device__ __forceinline__ float fast_tanh(float x) {
    x = fminf(fmaxf(x, -15.0f), 15.0f);
    float e = __expf(2.0f * x);
    return 1.0f - __fdividef(2.0f, e + 1.0f);
}

// ---------------------------------------------------------------------------
// Shared layout (float offsets)
//   ids  [2 rows][512]  (ints)                        1024
//   emb  [2 bufs][4 tok][2 rows][128]                 2048
//   xp   [2 bufs][4 tok][2 rows][128]                 2048
//   h    [2 bufs][2 rows][128]                         512
//   mlp  [2 rows][256]                                 512
//   stg  weight staging                               4096
// ---------------------------------------------------------------------------
#define SH_IDS  0
#define SH_EMB  1024
#define SH_XP   (1024 + 2048)
#define SH_H    (1024 + 2048 + 2048)
#define SH_MLP  (SH_H + 512)
#define SH_STG  (SH_MLP + 512)
#define SH_TOT  (SH_STG + 4096)      // 10240 floats = 40KB

// Barrier ids:
//   0        __syncthreads (256)
//   1        consumer h-publish bar (128)
//   3        producer-internal emb-visibility bar (128)
//   4 + buf  full[buf]  (256: 128 producers arrive, 128 consumers sync)
//   6 + buf  empty[buf] (256: 128 consumers arrive, 128 producers sync)

__global__ void __launch_bounds__(256, 1) fused_kernel(
    const int* __restrict__ x, const float* __restrict__ emb,
    const float* __restrict__ W_ih, const float* __restrict__ W_hh,
    const float* __restrict__ b_ih, const float* __restrict__ b_hh,
    const float* __restrict__ h0,
    const float* __restrict__ W1, const float* __restrict__ b1,
    const float* __restrict__ W2, const float* __restrict__ b2,
    float* __restrict__ logits, float* __restrict__ out_hidden)
{
    extern __shared__ float sh[];
    int*   s_ids = (int*)(sh + SH_IDS);
    float* s_emb = sh + SH_EMB;
    float* s_xp  = sh + SH_XP;
    float* s_h   = sh + SH_H;
    float* s_mlp = sh + SH_MLP;
    float* s_stg = sh + SH_STG;

    const int tid = threadIdx.x;
    const int b0  = blockIdx.x * 2;
    const bool is_prod = (tid >= 128);      // warps 4-7
    const int  myout   = is_prod ? (tid - 128) : tid;

    // ---- stage token ids for both rows
    for (int i = tid; i < 2 * TT; i += 256) {
        int row = i >> 9, t = i & 511;
        s_ids[i] = x[(size_t)(b0 + row) * TT + t];
    }

    // ---- load weights into registers:
    //      consumers get W_hh[myout][*], producers get W_ih[myout][*]
    unsigned long long wreg[64];
    for (int p = 0; p < 4; ++p) {
        for (int i = tid; i < 4096; i += 256)
            s_stg[i] = W_hh[p * 4096 + i];
        __syncthreads();
        if (!is_prod && (myout >> 5) == p) {
            const unsigned long long* r =
                (const unsigned long long*)(s_stg + (myout & 31) * 128);
            #pragma unroll
            for (int k = 0; k < 64; ++k) wreg[k] = r[k];
        }
        __syncthreads();
    }
    for (int p = 0; p < 4; ++p) {
        for (int i = tid; i < 4096; i += 256)
            s_stg[i] = W_ih[p * 4096 + i];
        __syncthreads();
        if (is_prod && (myout >> 5) == p) {
            const unsigned long long* r =
                (const unsigned long long*)(s_stg + (myout & 31) * 128);
            #pragma unroll
            for (int k = 0; k < 64; ++k) wreg[k] = r[k];
        }
        __syncthreads();
    }
    const float bias = b_ih[myout] + b_hh[myout];

    // ---- init h buffer 0 (both rows, by consumers)
    if (!is_prod) {
        s_h[myout]       = h0[(size_t)b0 * HIDDEN + myout];
        s_h[128 + myout] = h0[(size_t)(b0 + 1) * HIDDEN + myout];
    }
    __syncthreads();

    if (is_prod) {
        // ============ PRODUCER (R12/R14 structure, unchanged): thread owns
        // one W_ih row, computes xp for all 8 (token,row) pairs per batch.
        const int p = tid - 128;      // 0..127

        // prologue: stage emb batch 0 into buf 0 (cooperative, 128 threads)
        #pragma unroll
        for (int cc = 0; cc < 2; ++cc) {
            int c = p + cc * 128;
            int j = c >> 6, row = (c >> 5) & 1, part = c & 31;
            int id = s_ids[row * TT + 0 + j];
            cp_async16(s_emb + 0 * 1024 + j * 256 + row * 128 + part * 4,
                       emb + (size_t)id * HIDDEN + part * 4);
        }
        cp_commit();

        for (int bb = 0; bb < NBATCH; ++bb) {
            const int buf = bb & 1;
            if (bb >= 2) BAR_SYNC(6 + buf, 256);         // xp slot empty

            if (bb + 1 < NBATCH) {                       // stage batch bb+1
                const int nb = buf ^ 1, T = 4 * (bb + 1);
                #pragma unroll
                for (int cc = 0; cc < 2; ++cc) {
                    int c = p + cc * 128;
                    int j = c >> 6, row = (c >> 5) & 1, part = c & 31;
                    int id = s_ids[row * TT + T + j];
                    cp_async16(s_emb + nb * 1024 + j * 256 + row * 128 + part * 4,
                               emb + (size_t)id * HIDDEN + part * 4);
                }
                cp_commit();
                cp_wait1();                              // batch bb complete
            } else {
                cp_wait0();
            }
            BAR_SYNC(3, 128);                            // emb bb visible

            #pragma unroll
            for (int j = 0; j < 4; ++j) {
                #pragma unroll
                for (int r = 0; r < 2; ++r) {
                    const ulonglong2* e = (const ulonglong2*)
                        (s_emb + buf * 1024 + j * 256 + r * 128);
                    unsigned long long a0 = 0, a1 = 0, a2 = 0, a3 = 0;
                    #pragma unroll
                    for (int k = 0; k < 32; ++k) {
                        ulonglong2 v = e[k];             // broadcast LDS
                        if (k & 1) {
                            a2 = fma2(wreg[2 * k],     v.x, a2);
                            a3 = fma2(wreg[2 * k + 1], v.y, a3);
                        } else {
                            a0 = fma2(wreg[2 * k],     v.x, a0);
                            a1 = fma2(wreg[2 * k + 1], v.y, a1);
                        }
                    }
                    float2 u = unpack2(add2(add2(a0, a1), add2(a2, a3)));
                    s_xp[buf * 1024 + j * 256 + r * 128 + myout] =
                        u.x + u.y + bias;
                }
            }
            BAR_ARRIVE(4 + buf, 256);                    // xp slot full
        }
    } else {
        // ============ CONSUMER (dual-row, R10-style in-thread ILP):
        // thread owns output `myout` for BOTH rows; the two rows' chains
        // are independent and interleave; one 128-thread bar per step.
        float hc0 = 0.f, hc1 = 0.f;

        for (int bb = 0; bb < NBATCH; ++bb) {
            const int buf = bb & 1;
            BAR_SYNC(4 + buf, 256);                      // xp batch full

            float xv0[4], xv1[4];
            #pragma unroll
            for (int j = 0; j < 4; ++j) {
                xv0[j] = s_xp[buf * 1024 + j * 256 + myout];
                xv1[j] = s_xp[buf * 1024 + j * 256 + 128 + myout];
            }

            #pragma unroll
            for (int j = 0; j < 4; ++j) {
                const ulonglong2* h0v = (const ulonglong2*)
                    (s_h + (j & 1) * 256);
                const ulonglong2* h1v = (const ulonglong2*)
                    (s_h + (j & 1) * 256 + 128);

                unsigned long long a[8], b[8];
                #pragma unroll
                for (int i = 0; i < 8; ++i) { a[i] = 0ull; b[i] = 0ull; }
                #pragma unroll
                for (int k = 0; k < 32; ++k) {
                    ulonglong2 u = h0v[k];               // broadcast LDS
                    ulonglong2 v = h1v[k];
                    const int s = (k & 3) * 2;
                    a[s]     = fma2(wreg[2 * k],     u.x, a[s]);
                    a[s + 1] = fma2(wreg[2 * k + 1], u.y, a[s + 1]);
                    b[s]     = fma2(wreg[2 * k],     v.x, b[s]);
                    b[s + 1] = fma2(wreg[2 * k + 1], v.y, b[s + 1]);
                }
                unsigned long long ra =
                    add2(add2(a[0], a[1]), add2(a[2], a[3]));
                ra = add2(ra, add2(add2(a[4], a[5]), add2(a[6], a[7])));
                unsigned long long rb =
                    add2(add2(b[0], b[1]), add2(b[2], b[3]));
                rb = add2(rb, add2(add2(b[4], b[5]), add2(b[6], b[7])));
                float2 fa = unpack2(ra), fb = unpack2(rb);

                hc0 = fast_tanh(fa.x + fa.y + xv0[j]);
                hc1 = fast_tanh(fb.x + fb.y + xv1[j]);
                float* hn = s_h + ((j + 1) & 1) * 256;
                hn[myout]       = hc0;
                hn[128 + myout] = hc1;
                BAR_SYNC(1, 128);                        // publish h
            }
            BAR_ARRIVE(6 + buf, 256);                    // xp slot consumed
        }
        out_hidden[(size_t)b0 * HIDDEN + myout]       = hc0;
        out_hidden[(size_t)(b0 + 1) * HIDDEN + myout] = hc1;
    }

    // ============ fused MLP head (final h is in s_h buffer 0)
    __syncthreads();
    {
        const int m = tid;               // 0..255: one W1 row, both batch rows
        const float4* w4 = (const float4*)(W1 + (size_t)m * HIDDEN);
        float acc0 = b1[m], acc1 = acc0;
        const float4* h40 = (const float4*)(s_h);
        const float4* h41 = (const float4*)(s_h + 128);
        #pragma unroll 8
        for (int k4 = 0; k4 < 32; ++k4) {
            float4 w = __ldg(&w4[k4]);
            float4 u = h40[k4];
            float4 v = h41[k4];
            acc0 = fmaf(w.x, u.x, acc0); acc0 = fmaf(w.y, u.y, acc0);
            acc0 = fmaf(w.z, u.z, acc0); acc0 = fmaf(w.w, u.w, acc0);
            acc1 = fmaf(w.x, v.x, acc1); acc1 = fmaf(w.y, v.y, acc1);
            acc1 = fmaf(w.z, v.z, acc1); acc1 = fmaf(w.w, v.w, acc1);
        }
        s_mlp[m]       = fmaxf(acc0, 0.0f);
        s_mlp[256 + m] = fmaxf(acc1, 0.0f);
    }
    __syncthreads();

    if (tid < 8) {
        const int r = tid >> 2, cls = tid & 3;
        const float* mv = s_mlp + r * 256;
        const float* w2 = W2 + (size_t)cls * (2 * HIDDEN);
        float acc = b2[cls];
        #pragma unroll 8
        for (int k = 0; k < 256; ++k)
            acc = fmaf(mv[k], __ldg(&w2[k]), acc);
        logits[(size_t)(b0 + r) * NCLASS + cls] = acc;
    }
}

// ---------------------------------------------------------------------------
extern "C" void kernel_launch(void* const* d_in, const int* in_sizes, int n_in,
                              void* d_out, int out_size)
{
    const int*   x    = (const int*)  d_in[0];
    const float* h0   = (const float*)d_in[1];
    const float* emb  = (const float*)d_in[2];
    const float* W_ih = (const float*)d_in[3];
    const float* W_hh = (const float*)d_in[4];
    const float* b_ih = (const float*)d_in[5];
    const float* b_hh = (const float*)d_in[6];
    const float* W1   = (const float*)d_in[7];
    const float* b1   = (const float*)d_in[8];
    const float* W2   = (const float*)d_in[9];
    const float* b2   = (const float*)d_in[10];

    float* out    = (float*)d_out;
    float* logits = out;                 // [256*4]
    float* hidden = out + BB * NCLASS;   // [256*128]

    const int smem = SH_TOT * sizeof(float);   // 40KB

    fused_kernel<<<BB / 2, 256, smem>>>(x, emb, W_ih, W_hh, b_ih, b_hh, h0,
                                        W1, b1, W2, b2, logits, hidden);
}

// round 16
// speedup vs baseline: 1.6274x; 1.2138x over previous
#include <cuda_runtime.h>
#include <math.h>

#define HIDDEN  128
#define NCLASS  4
#define BB      256
#define TT      512
#define NBATCH  (TT / 4)     // 128 four-token batches

// ---------------------------------------------------------------- helpers
__device__ __forceinline__ unsigned smem_u32(const void* p) {
    return (unsigned)__cvta_generic_to_shared(p);
}
__device__ __forceinline__ void cp_async16(void* dst, const void* src) {
    asm volatile("cp.async.cg.shared.global [%0], [%1], 16;"
                 :: "r"(smem_u32(dst)), "l"(src));
}
__device__ __forceinline__ void cp_commit() {
    asm volatile("cp.async.commit_group;");
}
__device__ __forceinline__ void cp_wait1() {
    asm volatile("cp.async.wait_group 1;");
}
__device__ __forceinline__ void cp_wait0() {
    asm volatile("cp.async.wait_group 0;");
}
#define BAR_SYNC(id, cnt) \
    asm volatile("bar.sync %0, %1;" :: "r"(id), "r"(cnt) : "memory")
#define BAR_ARRIVE(id, cnt) \
    asm volatile("bar.arrive %0, %1;" :: "r"(id), "r"(cnt) : "memory")

__device__ __forceinline__ unsigned long long
fma2(unsigned long long a, unsigned long long b, unsigned long long c) {
    unsigned long long d;
    asm("fma.rn.f32x2 %0, %1, %2, %3;" : "=l"(d) : "l"(a), "l"(b), "l"(c));
    return d;
}
__device__ __forceinline__ unsigned long long
add2(unsigned long long a, unsigned long long b) {
    unsigned long long d;
    asm("add.rn.f32x2 %0, %1, %2;" : "=l"(d) : "l"(a), "l"(b));
    return d;
}
__device__ __forceinline__ float2 unpack2(unsigned long long v) {
    float2 r;
    asm("mov.b64 {%0, %1}, %2;" : "=f"(r.x), "=f"(r.y) : "l"(v));
    return r;
}
__device__ __forceinline__ unsigned long long pack2(float a, float b) {
    unsigned long long r;
    asm("mov.b64 %0, {%1, %2};" : "=l"(r) : "f"(a), "f"(b));
    return r;
}
__device__ __forceinline__ unsigned long long
shfl64_xor(unsigned long long v, int m) {
    unsigned lo, hi;
    asm("mov.b64 {%0, %1}, %2;" : "=r"(lo), "=r"(hi) : "l"(v));
    lo = __shfl_xor_sync(0xffffffffu, lo, m);
    hi = __shfl_xor_sync(0xffffffffu, hi, m);
    unsigned long long r;
    asm("mov.b64 %0, {%1, %2};" : "=l"(r) : "r"(lo), "r"(hi));
    return r;
}
__device__ __forceinline__ float fast_tanh(float x) {
    x = fminf(fmaxf(x, -15.0f), 15.0f);
    float e = __expf(2.0f * x);
    return 1.0f - __fdividef(2.0f, e + 1.0f);
}

// interleaved float offset within a 128-float row:
//   k -> ((k&31)>>2)*16 + (k>>5)*4 + (k&3)
// => quarter q's chunk c is the 16B at u2-index (c*4 + q); the 4 quarters'
//    chunks form one contiguous 64B span -> every LDS.128 = 1 wavefront.
__device__ __forceinline__ int ilv_off(int k) {
    return ((k & 31) >> 2) * 16 + (k >> 5) * 4 + (k & 3);
}

// Per-thread quarter dot for 4 outputs. src = (u2*)row_base + q.
// Loads the 32-float quarter once (8 LDS.128), reuses it for 4 outs.
__device__ __forceinline__ void dot4q(
    const ulonglong2* __restrict__ src,
    const unsigned long long (* __restrict__ wq)[16],
    float* __restrict__ s)
{
    ulonglong2 A[8];
    #pragma unroll
    for (int c = 0; c < 8; ++c) A[c] = src[c * 4];
    #pragma unroll
    for (int j = 0; j < 4; ++j) {
        unsigned long long a = 0, b = 0;
        #pragma unroll
        for (int c = 0; c < 8; ++c) {
            a = fma2(wq[j][2 * c],     A[c].x, a);
            b = fma2(wq[j][2 * c + 1], A[c].y, b);
        }
        float2 u = unpack2(add2(a, b));
        s[j] = u.x + u.y;
    }
}

// Cross-quarter reduce of 4 scalars (packed butterfly over lane bits 3,4).
// Returns this lane's selected value: out index = oid*4 + q.
__device__ __forceinline__ float qreduce4(const float* __restrict__ s, int q) {
    unsigned long long P01 = pack2(s[0], s[1]);
    unsigned long long P23 = pack2(s[2], s[3]);
    P01 = add2(P01, shfl64_xor(P01, 8));
    P01 = add2(P01, shfl64_xor(P01, 16));
    P23 = add2(P23, shfl64_xor(P23, 8));
    P23 = add2(P23, shfl64_xor(P23, 16));
    float2 u01 = unpack2(P01), u23 = unpack2(P23);
    return (q < 2) ? (q == 0 ? u01.x : u01.y)
                   : (q == 2 ? u23.x : u23.y);
}

// ---------------------------------------------------------------------------
// Shared layout (float offsets). emb and h are INTERLEAVED per 128-float row;
// xp and mlp are normal layout.
//   ids  [2 rows][512]  (ints)                        1024
//   emb  [2 bufs][4 tok][2 rows][128]                 2048
//   xp   [2 bufs][4 tok][2 rows][128]                 2048
//   h    [2 bufs][2 rows][128]                         512
//   mlp  [2 rows][256]                                 512
//   stg  weight staging / final-h scratch             4096
// ---------------------------------------------------------------------------
#define SH_IDS  0
#define SH_EMB  1024
#define SH_XP   (1024 + 2048)
#define SH_H    (1024 + 2048 + 2048)
#define SH_MLP  (SH_H + 512)
#define SH_STG  (SH_MLP + 512)
#define SH_TOT  (SH_STG + 4096)      // 10240 floats = 40KB

// Barrier ids:
//   0        __syncthreads (256)
//   1        consumer h-publish bar (128)
//   3        producer emb-visibility bar (128)
//   4 + buf  full[buf]  (256)
//   6 + buf  empty[buf] (256)

__global__ void __launch_bounds__(256, 1) fused_kernel(
    const int* __restrict__ x, const float* __restrict__ emb,
    const float* __restrict__ W_ih, const float* __restrict__ W_hh,
    const float* __restrict__ b_ih, const float* __restrict__ b_hh,
    const float* __restrict__ h0,
    const float* __restrict__ W1, const float* __restrict__ b1,
    const float* __restrict__ W2, const float* __restrict__ b2,
    float* __restrict__ logits, float* __restrict__ out_hidden)
{
    extern __shared__ float sh[];
    int*   s_ids = (int*)(sh + SH_IDS);
    float* s_emb = sh + SH_EMB;
    float* s_xp  = sh + SH_XP;
    float* s_h   = sh + SH_H;
    float* s_mlp = sh + SH_MLP;
    float* s_stg = sh + SH_STG;

    const int tid  = threadIdx.x;
    const int lane = tid & 31;
    const int w    = tid >> 5;              // 0..7
    const int b0   = blockIdx.x * 2;
    const bool is_prod = (w >= 4);
    const int q    = lane >> 3;             // K-quarter
    const int oid  = lane & 7;
    const int obase = (is_prod ? (w - 4) : w) * 32;
    const int out  = obase + oid * 4 + q;   // this lane's finalize output
    const int ilv  = ilv_off(out);

    // ---- stage token ids for both rows
    for (int i = tid; i < 2 * TT; i += 256) {
        int row = i >> 9, t = i & 511;
        s_ids[i] = x[(size_t)(b0 + row) * TT + t];
    }

    // ---- load weight slices: wq[j][c] = W[obase+oid*4+j][q*32 .. +32)
    //      consumers from W_hh, producers from W_ih (4 passes each).
    unsigned long long wq[4][16];
    for (int p = 0; p < 4; ++p) {
        for (int i = tid; i < 4096; i += 256)
            s_stg[i] = W_hh[p * 4096 + i];
        __syncthreads();
        if (!is_prod && (obase >> 5) == p) {
            #pragma unroll
            for (int j = 0; j < 4; ++j) {
                const unsigned long long* r = (const unsigned long long*)
                    (s_stg + (oid * 4 + j) * 128);
                #pragma unroll
                for (int c = 0; c < 16; ++c) wq[j][c] = r[q * 16 + c];
            }
        }
        __syncthreads();
    }
    for (int p = 0; p < 4; ++p) {
        for (int i = tid; i < 4096; i += 256)
            s_stg[i] = W_ih[p * 4096 + i];
        __syncthreads();
        if (is_prod && (obase >> 5) == p) {
            #pragma unroll
            for (int j = 0; j < 4; ++j) {
                const unsigned long long* r = (const unsigned long long*)
                    (s_stg + (oid * 4 + j) * 128);
                #pragma unroll
                for (int c = 0; c < 16; ++c) wq[j][c] = r[q * 16 + c];
            }
        }
        __syncthreads();
    }
    const float bias = b_ih[out] + b_hh[out];

    // ---- init h buffer 0 (interleaved), by consumer threads
    if (!is_prod) {
        s_h[ilv_off(tid & 127)]       = h0[(size_t)b0 * HIDDEN + (tid & 127)];
        s_h[128 + ilv_off(tid & 127)] = h0[(size_t)(b0 + 1) * HIDDEN + (tid & 127)];
    }
    __syncthreads();

    if (is_prod) {
        // ============ PRODUCER: xp[j][r][out] for all 8 (token,row) pairs.
        const int p = tid - 128;      // 0..127

        // prologue: stage emb batch 0 into buf 0 (interleaved)
        #pragma unroll
        for (int cc = 0; cc < 2; ++cc) {
            int c = p + cc * 128;
            int j = c >> 6, row = (c >> 5) & 1, part = c & 31;
            int id = s_ids[row * TT + 0 + j];
            cp_async16(s_emb + j * 256 + row * 128
                           + (part & 7) * 16 + (part >> 3) * 4,
                       emb + (size_t)id * HIDDEN + part * 4);
        }
        cp_commit();

        for (int bb = 0; bb < NBATCH; ++bb) {
            const int buf = bb & 1;
            if (bb >= 2) BAR_SYNC(6 + buf, 256);         // xp slot empty

            if (bb + 1 < NBATCH) {                       // stage batch bb+1
                const int nb = buf ^ 1, T = 4 * (bb + 1);
                #pragma unroll
                for (int cc = 0; cc < 2; ++cc) {
                    int c = p + cc * 128;
                    int j = c >> 6, row = (c >> 5) & 1, part = c & 31;
                    int id = s_ids[row * TT + T + j];
                    cp_async16(s_emb + nb * 1024 + j * 256 + row * 128
                                   + (part & 7) * 16 + (part >> 3) * 4,
                               emb + (size_t)id * HIDDEN + part * 4);
                }
                cp_commit();
                cp_wait1();
            } else {
                cp_wait0();
            }
            BAR_SYNC(3, 128);                            // emb bb visible

            #pragma unroll
            for (int j = 0; j < 4; ++j) {
                #pragma unroll
                for (int r = 0; r < 2; ++r) {
                    const ulonglong2* e = (const ulonglong2*)
                        (s_emb + buf * 1024 + j * 256 + r * 128) + q;
                    float s[4];
                    dot4q(e, wq, s);
                    float v = qreduce4(s, q);
                    s_xp[buf * 1024 + j * 256 + r * 128 + out] = v + bias;
                }
            }
            BAR_ARRIVE(4 + buf, 256);                    // xp slot full
        }
    } else {
        // ============ CONSUMER: dual-row recurrence, quarter-split.
        float hc0 = 0.f, hc1 = 0.f;

        for (int bb = 0; bb < NBATCH; ++bb) {
            const int buf = bb & 1;
            BAR_SYNC(4 + buf, 256);                      // xp batch full

            float xv0[4], xv1[4];
            #pragma unroll
            for (int j = 0; j < 4; ++j) {
                xv0[j] = s_xp[buf * 1024 + j * 256 + out];
                xv1[j] = s_xp[buf * 1024 + j * 256 + 128 + out];
            }

            #pragma unroll
            for (int j = 0; j < 4; ++j) {
                const ulonglong2* h0v = (const ulonglong2*)
                    (s_h + (j & 1) * 256) + q;
                const ulonglong2* h1v = (const ulonglong2*)
                    (s_h + (j & 1) * 256 + 128) + q;

                float s0[4], s1[4];
                dot4q(h0v, wq, s0);
                dot4q(h1v, wq, s1);
                float v0 = qreduce4(s0, q);
                float v1 = qreduce4(s1, q);

                hc0 = fast_tanh(v0 + xv0[j]);
                hc1 = fast_tanh(v1 + xv1[j]);
                float* hn = s_h + ((j + 1) & 1) * 256;
                hn[ilv]       = hc0;
                hn[128 + ilv] = hc1;
                BAR_SYNC(1, 128);                        // publish h
            }
            BAR_ARRIVE(6 + buf, 256);                    // xp slot consumed
        }
        out_hidden[(size_t)b0 * HIDDEN + out]       = hc0;
        out_hidden[(size_t)(b0 + 1) * HIDDEN + out] = hc1;
        // final h, normal layout, for the head
        s_stg[out]       = hc0;
        s_stg[128 + out] = hc1;
    }

    // ============ fused MLP head (final h in s_stg, normal layout)
    __syncthreads();
    {
        const int m = tid;               // 0..255: one W1 row, both batch rows
        const float4* w4 = (const float4*)(W1 + (size_t)m * HIDDEN);
        float acc0 = b1[m], acc1 = acc0;
        const float4* h40 = (const float4*)(s_stg);
        const float4* h41 = (const float4*)(s_stg + 128);
        #pragma unroll 8
        for (int k4 = 0; k4 < 32; ++k4) {
            float4 ww = __ldg(&w4[k4]);
            float4 u = h40[k4];
            float4 v = h41[k4];
            acc0 = fmaf(ww.x, u.x, acc0); acc0 = fmaf(ww.y, u.y, acc0);
            acc0 = fmaf(ww.z, u.z, acc0); acc0 = fmaf(ww.w, u.w, acc0);
            acc1 = fmaf(ww.x, v.x, acc1); acc1 = fmaf(ww.y, v.y, acc1);
            acc1 = fmaf(ww.z, v.z, acc1); acc1 = fmaf(ww.w, v.w, acc1);
        }
        s_mlp[m]       = fmaxf(acc0, 0.0f);
        s_mlp[256 + m] = fmaxf(acc1, 0.0f);
    }
    __syncthreads();

    if (tid < 8) {
        const int r = tid >> 2, cls = tid & 3;
        const float* mv = s_mlp + r * 256;
        const float* w2 = W2 + (size_t)cls * (2 * HIDDEN);
        float acc = b2[cls];
        #pragma unroll 8
        for (int k = 0; k < 256; ++k)
            acc = fmaf(mv[k], __ldg(&w2[k]), acc);
        logits[(size_t)(b0 + r) * NCLASS + cls] = acc;
    }
}

// ---------------------------------------------------------------------------
extern "C" void kernel_launch(void* const* d_in, const int* in_sizes, int n_in,
                              void* d_out, int out_size)
{
    const int*   x    = (const int*)  d_in[0];
    const float* h0   = (const float*)d_in[1];
    const float* emb  = (const float*)d_in[2];
    const float* W_ih = (const float*)d_in[3];
    const float* W_hh = (const float*)d_in[4];
    const float* b_ih = (const float*)d_in[5];
    const float* b_hh = (const float*)d_in[6];
    const float* W1   = (const float*)d_in[7];
    const float* b1   = (const float*)d_in[8];
    const float* W2   = (const float*)d_in[9];
    const float* b2   = (const float*)d_in[10];

    float* out    = (float*)d_out;
    float* logits = out;                 // [256*4]
    float* hidden = out + BB * NCLASS;   // [256*128]

    const int smem = SH_TOT * sizeof(float);   // 40KB

    fused_kernel<<<BB / 2, 256, smem>>>(x, emb, W_ih, W_hh, b_ih, b_hh, h0,
                                        W1, b1, W2, b2, logits, hidden);
}